// round 7
// baseline (speedup 1.0000x reference)
#include <cuda_runtime.h>
#include <math.h>

#define NN 6000
#define EE 100000

// ---------------- device scratch (static, no allocation) ----------------
__device__ int g_degT[2 * NN];     // per (node,type) counts; re-zeroed by scan each launch
__device__ int g_rowptr[NN + 1];
__device__ int g_mid[NN];          // rowptr[n] + deg_type0[n]
__device__ __align__(16) float g_inv[2 * NN];    // 1/max(cnt,1) per (node,type)
__device__ int g_rank[EE];
__device__ int g_es[EE];           // packed per CSR slot: e | (src<<17); type implied by slot<mid

__device__ __align__(16) float g_W0[2 * NN * 32];
__device__ __align__(16) float g_Wl1[2 * 32 * 64];
__device__ __align__(16) float g_Wl2[2 * 64 * 64];
__device__ __align__(16) float g_Wl3[2 * 64 * 32];
__device__ __align__(16) float g_hrA[2 * NN * 64];
__device__ __align__(16) float g_hrB[2 * NN * 64];
__device__ __align__(16) float g_rootout[NN * 64];
__device__ __align__(16) float g_rootout3[NN * 32];
__device__ __align__(16) float g_h[NN * 512];
__device__ float4 g_attnS[NN];     // {asv, e^asv, e^{0.2 asv}, 0}
__device__ float4 g_attnD[NN];     // {adv, e^adv, e^{0.2 adv}, exself}
__device__ __align__(16) float g_pt[NN * 128];
__device__ __align__(16) float g_pb[NN * 128];

#define ES_S(v) ((v) >> 17)
#define ES_E(v) ((v) & 0x1FFFF)

// ---------------- kernel 1: relation-weight precompute + per-type degree count ----------------
#define W0_CNT (2 * NN * 32)
#define WL1_CNT (2 * 32 * 64)
#define WL2_CNT (2 * 64 * 64)
#define WL3_CNT (2 * 64 * 32)
#define PRE_CNT (W0_CNT + WL1_CNT + WL2_CNT + WL3_CNT)
#define PRE_BLOCKS (PRE_CNT / 256)
#define CNT_BLOCKS ((EE + 255) / 256)

__global__ void pre_count_kernel(const float* __restrict__ basis0, const float* __restrict__ comp0,
                                 const float* __restrict__ basis1, const float* __restrict__ comp1,
                                 const float* __restrict__ basis2, const float* __restrict__ comp2,
                                 const float* __restrict__ basis3, const float* __restrict__ comp3,
                                 const int* __restrict__ dst, const int* __restrict__ et) {
    int bid = blockIdx.x;
    if (bid >= PRE_BLOCKS) {
        int e = (bid - PRE_BLOCKS) * 256 + threadIdx.x;
        if (e < EE) g_rank[e] = atomicAdd(&g_degT[2 * dst[e] + et[e]], 1);
        return;
    }
    int idx = bid * 256 + threadIdx.x;
    if (idx < W0_CNT) {
        int per = NN * 32;
        int r = idx / per, rem = idx - r * per;
        float v = 0.f;
#pragma unroll
        for (int b = 0; b < 4; b++) v += comp0[r * 4 + b] * basis0[b * per + rem];
        g_W0[idx] = v;
        return;
    }
    idx -= W0_CNT;
    if (idx < WL1_CNT) {
        int per = 32 * 64;
        int r = idx / per, rem = idx - r * per;
        float v = 0.f;
#pragma unroll
        for (int b = 0; b < 4; b++) v += comp1[r * 4 + b] * basis1[b * per + rem];
        g_Wl1[idx] = v;
        return;
    }
    idx -= WL1_CNT;
    if (idx < WL2_CNT) {
        int per = 64 * 64;
        int r = idx / per, rem = idx - r * per;
        float v = 0.f;
#pragma unroll
        for (int b = 0; b < 4; b++) v += comp2[r * 4 + b] * basis2[b * per + rem];
        g_Wl2[idx] = v;
        return;
    }
    idx -= WL2_CNT;
    {
        int per = 64 * 32;
        int r = idx / per, rem = idx - r * per;
        float v = 0.f;
#pragma unroll
        for (int b = 0; b < 4; b++) v += comp3[r * 4 + b] * basis3[b * per + rem];
        g_Wl3[idx] = v;
    }
}

// ---------------- kernel 2: single-pass scan; emits rowptr/mid/inv, re-zeroes degT ----------------
__global__ void scan_kernel() {
    __shared__ int swsum[32];
    int tid = threadIdx.x, lane = tid & 31, wid = tid >> 5;
    int base = tid * 6;
    int d0[6], d1[6];
    int s = 0;
#pragma unroll
    for (int j = 0; j < 6; j++) {
        int i = base + j;
        d0[j] = (i < NN) ? g_degT[2 * i] : 0;
        d1[j] = (i < NN) ? g_degT[2 * i + 1] : 0;
        s += d0[j] + d1[j];
    }
    int x = s;
#pragma unroll
    for (int off = 1; off < 32; off <<= 1) {
        int t = __shfl_up_sync(0xffffffffu, x, off);
        if (lane >= off) x += t;
    }
    if (lane == 31) swsum[wid] = x;
    __syncthreads();
    if (wid == 0) {
        int y = swsum[lane];
#pragma unroll
        for (int off = 1; off < 32; off <<= 1) {
            int t = __shfl_up_sync(0xffffffffu, y, off);
            if (lane >= off) y += t;
        }
        swsum[lane] = y;
    }
    __syncthreads();
    int run = x - s + (wid ? swsum[wid - 1] : 0);
#pragma unroll
    for (int j = 0; j < 6; j++) {
        int i = base + j;
        if (i < NN) {
            g_mid[i] = run + d0[j];
            g_inv[2 * i] = 1.f / fmaxf((float)d0[j], 1.f);
            g_inv[2 * i + 1] = 1.f / fmaxf((float)d1[j], 1.f);
            run += d0[j] + d1[j];
            g_rowptr[i + 1] = run;
            g_degT[2 * i] = 0;
            g_degT[2 * i + 1] = 0;
        }
    }
    if (tid == 0) g_rowptr[0] = 0;
}

// ---------------- kernel 3: atomic-free scatter into type-sorted CSR ----------------
__global__ void scatter_kernel(const int* __restrict__ src, const int* __restrict__ dst,
                               const int* __restrict__ et) {
    int e = blockIdx.x * blockDim.x + threadIdx.x;
    if (e < EE) {
        int d = dst[e], t = et[e];
        int p = (t ? g_mid[d] : g_rowptr[d]) + g_rank[e];
        g_es[p] = e | (src[e] << 17);
    }
}

// ---------------- pipelined two-segment aggregation helper ----------------
template <int W>
__device__ __forceinline__ void agg_seg(const float* __restrict__ plane,
                                        int beg, int mid, int end, int lane,
                                        float& a0, float& a1) {
    const float* p1 = plane + (size_t)NN * W;
    int k = beg;
    if (end - k >= 8) {
        int pv[8];
#pragma unroll
        for (int i = 0; i < 8; i++) pv[i] = g_es[k + i];
        while (k + 16 <= end) {
            int nv[8];
#pragma unroll
            for (int i = 0; i < 8; i++) nv[i] = g_es[k + 8 + i];
#pragma unroll
            for (int i = 0; i < 8; i++) {
                const float* pl = (k + i < mid) ? plane : p1;
                float f = pl[(size_t)ES_S(pv[i]) * W + lane];
                if (k + i < mid) a0 += f; else a1 += f;
            }
#pragma unroll
            for (int i = 0; i < 8; i++) pv[i] = nv[i];
            k += 8;
        }
#pragma unroll
        for (int i = 0; i < 8; i++) {
            const float* pl = (k + i < mid) ? plane : p1;
            float f = pl[(size_t)ES_S(pv[i]) * W + lane];
            if (k + i < mid) a0 += f; else a1 += f;
        }
        k += 8;
    }
    for (; k < end; k++) {
        const float* pl = (k < mid) ? plane : p1;
        float f = pl[(size_t)ES_S(g_es[k]) * W + lane];
        if (k < mid) a0 += f; else a1 += f;
    }
}

// ---------------- kernel 4: layer-0 agg (identity input) + dense1 fused ----------------
__global__ void l0d1_kernel(const float* __restrict__ root0, const float* __restrict__ rbias0,
                            const float* __restrict__ root1, const float* __restrict__ rbias1) {
    __shared__ float sx[8][32];
    int tid = threadIdx.x, w = tid >> 5, lane = tid & 31;
    int node = blockIdx.x * 8 + w;
    {
        int beg = g_rowptr[node], mid = g_mid[node], end = g_rowptr[node + 1];
        float a0 = 0.f, a1 = 0.f;
        agg_seg<32>(g_W0, beg, mid, end, lane, a0, a1);
        float2 iv = *(const float2*)(g_inv + 2 * node);
        float out = root0[node * 32 + lane] + rbias0[lane] + a0 * iv.x + a1 * iv.y;
        sx[w][lane] = tanhf(out);
    }
    __syncthreads();
#pragma unroll
    for (int t = tid; t < 512; t += 256) {
        int ln = t >> 6, o = t & 63;
        int nn = blockIdx.x * 8 + ln;
        float a0 = 0.f, a1 = 0.f, ar = 0.f;
#pragma unroll 8
        for (int i = 0; i < 32; i++) {
            float xv = sx[ln][i];
            a0 += xv * g_Wl1[i * 64 + o];
            a1 += xv * g_Wl1[32 * 64 + i * 64 + o];
            ar += xv * root1[i * 64 + o];
        }
        g_hrA[nn * 64 + o] = a0;
        g_hrA[NN * 64 + nn * 64 + o] = a1;
        g_rootout[nn * 64 + o] = ar + rbias1[o];
    }
}

// ---------------- kernel 5: agg1 + dense2 fused ----------------
__global__ void a1d2_kernel(const float* __restrict__ root2, const float* __restrict__ rbias2) {
    __shared__ float sx[4][64];
    int tid = threadIdx.x;
    int ln = tid >> 6, o = tid & 63;
    int node = blockIdx.x * 4 + ln;
    {
        int beg = g_rowptr[node], mid = g_mid[node], end = g_rowptr[node + 1];
        float a0 = 0.f, a1 = 0.f;
        agg_seg<64>(g_hrA, beg, mid, end, o, a0, a1);
        float2 iv = *(const float2*)(g_inv + 2 * node);
        float out = g_rootout[node * 64 + o] + a0 * iv.x + a1 * iv.y;
        sx[ln][o] = tanhf(out);
    }
    __syncthreads();
    float a0 = 0.f, a1 = 0.f, ar = 0.f;
#pragma unroll 8
    for (int i = 0; i < 64; i++) {
        float xv = sx[ln][i];
        a0 += xv * g_Wl2[i * 64 + o];
        a1 += xv * g_Wl2[64 * 64 + i * 64 + o];
        ar += xv * root2[i * 64 + o];
    }
    g_hrB[node * 64 + o] = a0;
    g_hrB[NN * 64 + node * 64 + o] = a1;
    g_rootout[node * 64 + o] = ar + rbias2[o];
}

// ---------------- kernel 6: agg2 + dense3 fused ----------------
__global__ void a2d3_kernel(const float* __restrict__ root3, const float* __restrict__ rbias3) {
    __shared__ float sx[4][64];
    int tid = threadIdx.x;
    int ln = tid >> 6, o = tid & 63;
    int node = blockIdx.x * 4 + ln;
    {
        int beg = g_rowptr[node], mid = g_mid[node], end = g_rowptr[node + 1];
        float a0 = 0.f, a1 = 0.f;
        agg_seg<64>(g_hrB, beg, mid, end, o, a0, a1);
        float2 iv = *(const float2*)(g_inv + 2 * node);
        float out = g_rootout[node * 64 + o] + a0 * iv.x + a1 * iv.y;
        sx[ln][o] = tanhf(out);
    }
    __syncthreads();
    if (tid < 128) {
        int ln3 = tid >> 5, o3 = tid & 31;
        int nn = blockIdx.x * 4 + ln3;
        float a0 = 0.f, a1 = 0.f, ar = 0.f;
#pragma unroll 8
        for (int i = 0; i < 64; i++) {
            float xv = sx[ln3][i];
            a0 += xv * g_Wl3[i * 32 + o3];
            a1 += xv * g_Wl3[64 * 32 + i * 32 + o3];
            ar += xv * root3[i * 32 + o3];
        }
        g_hrA[nn * 32 + o3] = a0;
        g_hrA[NN * 32 + nn * 32 + o3] = a1;
        g_rootout3[nn * 32 + o3] = ar + rbias3[o3];
    }
}

// ---------------- kernel 7: agg3 + GAT h GEMM + attention-exp precompute, fused ----------------
__global__ void agg3_gath_kernel(const float* __restrict__ gw,
                                 const float* __restrict__ as, const float* __restrict__ ad) {
    __shared__ __align__(16) float sx[16][32];
    __shared__ float s_as[16], s_ad[16];
    int tid = threadIdx.x;  // 512
    int node0 = blockIdx.x * 16;
    int w = tid >> 5, lane = tid & 31;
    {
        int node = node0 + w;
        int beg = g_rowptr[node], mid = g_mid[node], end = g_rowptr[node + 1];
        float a0 = 0.f, a1 = 0.f;
        agg_seg<32>(g_hrA, beg, mid, end, lane, a0, a1);
        float2 iv = *(const float2*)(g_inv + 2 * node);
        float out = g_rootout3[node * 32 + lane] + a0 * iv.x + a1 * iv.y;
        sx[w][lane] = tanhf(out);
    }
    if (tid < 16) { s_as[tid] = 0.f; s_ad[tid] = 0.f; }
    __syncthreads();
    int cg = tid & 127;
    int ng = tid >> 7;
    int col4 = cg * 4;
    int nbase = ng * 4;
    float acc[4][4];
#pragma unroll
    for (int a = 0; a < 4; a++)
#pragma unroll
        for (int b = 0; b < 4; b++) acc[a][b] = 0.f;
#pragma unroll 8
    for (int i = 0; i < 32; i++) {
        float4 wv = *(const float4*)(gw + i * 512 + col4);
        float x0 = sx[nbase + 0][i], x1 = sx[nbase + 1][i];
        float x2 = sx[nbase + 2][i], x3 = sx[nbase + 3][i];
        acc[0][0] += x0 * wv.x; acc[0][1] += x0 * wv.y; acc[0][2] += x0 * wv.z; acc[0][3] += x0 * wv.w;
        acc[1][0] += x1 * wv.x; acc[1][1] += x1 * wv.y; acc[1][2] += x1 * wv.z; acc[1][3] += x1 * wv.w;
        acc[2][0] += x2 * wv.x; acc[2][1] += x2 * wv.y; acc[2][2] += x2 * wv.z; acc[2][3] += x2 * wv.w;
        acc[3][0] += x3 * wv.x; acc[3][1] += x3 * wv.y; acc[3][2] += x3 * wv.z; acc[3][3] += x3 * wv.w;
    }
#pragma unroll
    for (int a = 0; a < 4; a++) {
        int nn = node0 + nbase + a;
        float4 o = make_float4(acc[a][0], acc[a][1], acc[a][2], acc[a][3]);
        *(float4*)(g_h + (size_t)nn * 512 + col4) = o;
    }
    float4 av = *(const float4*)(as + col4);
    float4 dv = *(const float4*)(ad + col4);
#pragma unroll
    for (int a = 0; a < 4; a++) {
        float ps = acc[a][0] * av.x + acc[a][1] * av.y + acc[a][2] * av.z + acc[a][3] * av.w;
        float pd = acc[a][0] * dv.x + acc[a][1] * dv.y + acc[a][2] * dv.z + acc[a][3] * dv.w;
#pragma unroll
        for (int off = 16; off; off >>= 1) {
            ps += __shfl_down_sync(0xffffffffu, ps, off);
            pd += __shfl_down_sync(0xffffffffu, pd, off);
        }
        if (lane == 0) {
            atomicAdd(&s_as[nbase + a], ps);
            atomicAdd(&s_ad[nbase + a], pd);
        }
    }
    __syncthreads();
    if (tid < 16) {
        int nn = node0 + tid;
        float asv = s_as[tid], adv = s_ad[tid];
        float al = asv + adv;
        float exself = expf(al > 0.f ? al : 0.2f * al);
        g_attnS[nn] = make_float4(asv, expf(asv), expf(0.2f * asv), 0.f);
        g_attnD[nn] = make_float4(adv, expf(adv), expf(0.2f * adv), exself);
    }
}

// ---------------- kernel 8: GAT softmax-agg (warp/node) + w1 GEMM (f32x2), fused ----------------
#define GA_NODES 32
#define SXPAD 34                       // even stride: keeps float2 rows 8B-aligned
#define SXT(i, nloc) ((i) * SXPAD + (nloc))
#define GA_SMEM (512 * SXPAD * 4)

__global__ void gatagg_ptpb_kernel(const float* __restrict__ gbias,
                                   const float* __restrict__ w1, const float* __restrict__ b1) {
    extern __shared__ __align__(16) float sxT[];  // [512][SXPAD] transposed tile
    int tid = threadIdx.x;          // 256
    int node0 = blockIdx.x * GA_NODES;
    int w = tid >> 5, lane = tid & 31;
    const float4* h4 = (const float4*)g_h;
    // phase A: softmax-aggregate, warp per node (4 nodes/warp)
    for (int j = 0; j < 4; j++) {
        int local = w * 4 + j;
        int n = node0 + local;
        if (n >= NN) break;
        float4 adn = g_attnD[n];
        float advn = adn.x, F1 = adn.y, F2 = adn.z, exself = adn.w;
        int beg = g_rowptr[n], end = g_rowptr[n + 1];
        float4 acc[4];
#pragma unroll
        for (int q = 0; q < 4; q++) {
            float4 hv = h4[(size_t)n * 128 + lane + 32 * q];
            acc[q].x = exself * hv.x; acc[q].y = exself * hv.y;
            acc[q].z = exself * hv.z; acc[q].w = exself * hv.w;
        }
        float dsum = exself;
        int k = beg;
        for (; k + 2 <= end; k += 2) {
            int v0 = g_es[k], v1 = g_es[k + 1];
            int s0 = ES_S(v0), s1 = ES_S(v1);
            float4 A0 = g_attnS[s0];
            float4 A1 = g_attnS[s1];
            float ex0 = (A0.x + advn > 0.f) ? A0.y * F1 : A0.z * F2;
            float ex1 = (A1.x + advn > 0.f) ? A1.y * F1 : A1.z * F2;
            dsum += ex0 + ex1;
#pragma unroll
            for (int q = 0; q < 4; q++) {
                float4 h0 = h4[(size_t)s0 * 128 + lane + 32 * q];
                float4 h1 = h4[(size_t)s1 * 128 + lane + 32 * q];
                acc[q].x += ex0 * h0.x + ex1 * h1.x;
                acc[q].y += ex0 * h0.y + ex1 * h1.y;
                acc[q].z += ex0 * h0.z + ex1 * h1.z;
                acc[q].w += ex0 * h0.w + ex1 * h1.w;
            }
        }
        if (k < end) {
            int v = g_es[k];
            int s = ES_S(v);
            float4 A = g_attnS[s];
            float ex = (A.x + advn > 0.f) ? A.y * F1 : A.z * F2;
            dsum += ex;
#pragma unroll
            for (int q = 0; q < 4; q++) {
                float4 hv = h4[(size_t)s * 128 + lane + 32 * q];
                acc[q].x += ex * hv.x; acc[q].y += ex * hv.y;
                acc[q].z += ex * hv.z; acc[q].w += ex * hv.w;
            }
        }
        float inv = 1.f / fmaxf(dsum, 1e-16f);
#pragma unroll
        for (int q = 0; q < 4; q++) {
            float4 gb = ((const float4*)gbias)[lane + 32 * q];
            int c = 4 * (lane + 32 * q);
            sxT[SXT(c + 0, local)] = fmaxf(acc[q].x * inv + gb.x, 0.f);
            sxT[SXT(c + 1, local)] = fmaxf(acc[q].y * inv + gb.y, 0.f);
            sxT[SXT(c + 2, local)] = fmaxf(acc[q].z * inv + gb.z, 0.f);
            sxT[SXT(c + 3, local)] = fmaxf(acc[q].w * inv + gb.w, 0.f);
        }
    }
    __syncthreads();
    // phase B: GEMM 1024->256 split as two 512-col halves, f32x2 packed FMA
    int cg = tid & 63, ng = tid >> 6;
    int half = cg >> 5, col4 = (cg & 31) * 4;
    const float* wp = w1 + (half ? 512 * 128 : 0) + col4;
    int nbase = ng * 8;
    unsigned long long acc2[4][4];
#pragma unroll
    for (int p = 0; p < 4; p++)
#pragma unroll
        for (int c = 0; c < 4; c++) acc2[p][c] = 0ull;
#pragma unroll 2
    for (int i = 0; i < 512; i++) {
        float4 wv = *(const float4*)(wp + i * 128);
        unsigned long long wxx, wyy, wzz, www;
        asm("mov.b64 %0, {%1, %1};" : "=l"(wxx) : "f"(wv.x));
        asm("mov.b64 %0, {%1, %1};" : "=l"(wyy) : "f"(wv.y));
        asm("mov.b64 %0, {%1, %1};" : "=l"(wzz) : "f"(wv.z));
        asm("mov.b64 %0, {%1, %1};" : "=l"(www) : "f"(wv.w));
        const float* row = &sxT[SXT(i, nbase)];
#pragma unroll
        for (int p = 0; p < 4; p++) {
            float2 x2 = *(const float2*)(row + 2 * p);
            unsigned long long xp;
            asm("mov.b64 %0, {%1, %2};" : "=l"(xp) : "f"(x2.x), "f"(x2.y));
            asm("fma.rn.f32x2 %0, %1, %2, %0;" : "+l"(acc2[p][0]) : "l"(xp), "l"(wxx));
            asm("fma.rn.f32x2 %0, %1, %2, %0;" : "+l"(acc2[p][1]) : "l"(xp), "l"(wyy));
            asm("fma.rn.f32x2 %0, %1, %2, %0;" : "+l"(acc2[p][2]) : "l"(xp), "l"(wzz));
            asm("fma.rn.f32x2 %0, %1, %2, %0;" : "+l"(acc2[p][3]) : "l"(xp), "l"(www));
        }
    }
    float4 bb = half ? make_float4(0.f, 0.f, 0.f, 0.f) : *(const float4*)(b1 + col4);
    float* obase = half ? g_pb : g_pt;
#pragma unroll
    for (int p = 0; p < 4; p++) {
        float lo[4], hi[4];
#pragma unroll
        for (int c = 0; c < 4; c++)
            asm("mov.b64 {%0, %1}, %2;" : "=f"(lo[c]), "=f"(hi[c]) : "l"(acc2[p][c]));
        int n0 = node0 + nbase + 2 * p;
        if (n0 < NN)
            *(float4*)(obase + (size_t)n0 * 128 + col4) =
                make_float4(lo[0] + bb.x, lo[1] + bb.y, lo[2] + bb.z, lo[3] + bb.w);
        if (n0 + 1 < NN)
            *(float4*)(obase + (size_t)(n0 + 1) * 128 + col4) =
                make_float4(hi[0] + bb.x, hi[1] + bb.y, hi[2] + bb.z, hi[3] + bb.w);
    }
}

// ---------------- kernel 9: per-edge output, CSR order ----------------
__global__ void edge_out_kernel(const float* __restrict__ w2, const float* __restrict__ b2,
                                float* __restrict__ out) {
    int tid = threadIdx.x, w = tid >> 5, lane = tid & 31;
    int node = blockIdx.x * 8 + w;
    int beg = g_rowptr[node], end = g_rowptr[node + 1];
    if (beg == end) return;
    const float4* pt4 = (const float4*)g_pt;
    float4 pbv = ((const float4*)g_pb)[(size_t)node * 32 + lane];
    float4 wv = ((const float4*)w2)[lane];
    float bias = b2[0];
    int k = beg;
    for (; k + 2 <= end; k += 2) {
        int v0 = g_es[k], v1 = g_es[k + 1];
        float4 a0 = pt4[(size_t)ES_S(v0) * 32 + lane];
        float4 a1 = pt4[(size_t)ES_S(v1) * 32 + lane];
        float r0 = fmaxf(a0.x + pbv.x, 0.f) * wv.x + fmaxf(a0.y + pbv.y, 0.f) * wv.y
                 + fmaxf(a0.z + pbv.z, 0.f) * wv.z + fmaxf(a0.w + pbv.w, 0.f) * wv.w;
        float r1 = fmaxf(a1.x + pbv.x, 0.f) * wv.x + fmaxf(a1.y + pbv.y, 0.f) * wv.y
                 + fmaxf(a1.z + pbv.z, 0.f) * wv.z + fmaxf(a1.w + pbv.w, 0.f) * wv.w;
#pragma unroll
        for (int off = 16; off; off >>= 1) {
            r0 += __shfl_down_sync(0xffffffffu, r0, off);
            r1 += __shfl_down_sync(0xffffffffu, r1, off);
        }
        if (lane == 0) {
            out[ES_E(v0)] = 1.f / (1.f + expf(-(r0 + bias)));
            out[ES_E(v1)] = 1.f / (1.f + expf(-(r1 + bias)));
        }
    }
    if (k < end) {
        int v = g_es[k];
        float4 a = pt4[(size_t)ES_S(v) * 32 + lane];
        float r = fmaxf(a.x + pbv.x, 0.f) * wv.x + fmaxf(a.y + pbv.y, 0.f) * wv.y
                + fmaxf(a.z + pbv.z, 0.f) * wv.z + fmaxf(a.w + pbv.w, 0.f) * wv.w;
#pragma unroll
        for (int off = 16; off; off >>= 1) r += __shfl_down_sync(0xffffffffu, r, off);
        if (lane == 0) out[ES_E(v)] = 1.f / (1.f + expf(-(r + bias)));
    }
}

// ---------------- launch ----------------
extern "C" void kernel_launch(void* const* d_in, const int* in_sizes, int n_in,
                              void* d_out, int out_size) {
    int off, iE, iT;
    if (in_sizes[0] == 2 * EE) { off = 2; iE = 0; iT = 1; }
    else                       { off = 0; iE = 24; iT = 25; }
    const int* ei = (const int*)d_in[iE];
    const int* et = (const int*)d_in[iT];
    const int* src = ei;
    const int* dst = ei + EE;
    const float* basis0 = (const float*)d_in[off + 0];
    const float* comp0  = (const float*)d_in[off + 1];
    const float* root0  = (const float*)d_in[off + 2];
    const float* rbias0 = (const float*)d_in[off + 3];
    const float* basis1 = (const float*)d_in[off + 4];
    const float* comp1  = (const float*)d_in[off + 5];
    const float* root1  = (const float*)d_in[off + 6];
    const float* rbias1 = (const float*)d_in[off + 7];
    const float* basis2 = (const float*)d_in[off + 8];
    const float* comp2  = (const float*)d_in[off + 9];
    const float* root2  = (const float*)d_in[off + 10];
    const float* rbias2 = (const float*)d_in[off + 11];
    const float* basis3 = (const float*)d_in[off + 12];
    const float* comp3  = (const float*)d_in[off + 13];
    const float* root3  = (const float*)d_in[off + 14];
    const float* rbias3 = (const float*)d_in[off + 15];
    const float* gw  = (const float*)d_in[off + 16];
    const float* gas = (const float*)d_in[off + 17];
    const float* gad = (const float*)d_in[off + 18];
    const float* gb  = (const float*)d_in[off + 19];
    const float* w1  = (const float*)d_in[off + 20];
    const float* b1  = (const float*)d_in[off + 21];
    const float* w2  = (const float*)d_in[off + 22];
    const float* b2  = (const float*)d_in[off + 23];
    float* out = (float*)d_out;

    cudaFuncSetAttribute(gatagg_ptpb_kernel,
                         cudaFuncAttributeMaxDynamicSharedMemorySize, GA_SMEM);

    pre_count_kernel<<<PRE_BLOCKS + CNT_BLOCKS, 256>>>(basis0, comp0, basis1, comp1,
                                                       basis2, comp2, basis3, comp3, dst, et);
    scan_kernel<<<1, 1024>>>();
    scatter_kernel<<<CNT_BLOCKS, 256>>>(src, dst, et);

    l0d1_kernel<<<NN / 8, 256>>>(root0, rbias0, root1, rbias1);
    a1d2_kernel<<<NN / 4, 256>>>(root2, rbias2);
    a2d3_kernel<<<NN / 4, 256>>>(root3, rbias3);

    agg3_gath_kernel<<<NN / 16, 512>>>(gw, gas, gad);
    gatagg_ptpb_kernel<<<(NN + GA_NODES - 1) / GA_NODES, 256, GA_SMEM>>>(gb, w1, b1);
    edge_out_kernel<<<NN / 8, 256>>>(w2, b2, out);
}

// round 8
// speedup vs baseline: 1.0226x; 1.0226x over previous
#include <cuda_runtime.h>
#include <math.h>

#define NN 6000
#define EE 100000

// ---------------- device scratch (static, no allocation) ----------------
__device__ int g_degT[2 * NN];     // per (node,type) counts; re-zeroed by scan each launch
__device__ int g_rowptr[NN + 1];
__device__ int g_mid[NN];          // rowptr[n] + deg_type0[n]
__device__ __align__(16) float g_inv[2 * NN];    // 1/max(cnt,1) per (node,type)
__device__ int g_rank[EE];
__device__ int g_es[EE];           // packed per CSR slot: e | (src<<17); type implied by slot<mid

__device__ __align__(16) float g_W0[2 * NN * 32];
__device__ __align__(16) float g_Wl1[2 * 32 * 64];
__device__ __align__(16) float g_Wl2[2 * 64 * 64];
__device__ __align__(16) float g_Wl3[2 * 64 * 32];
__device__ __align__(16) float g_hrA[2 * NN * 64];
__device__ __align__(16) float g_hrB[2 * NN * 64];
__device__ __align__(16) float g_rootout[NN * 64];
__device__ __align__(16) float g_rootout3[NN * 32];
__device__ __align__(16) float g_h[NN * 512];
__device__ float4 g_attnS[NN];     // {asv, e^asv, e^{0.2 asv}, 0}
__device__ float4 g_attnD[NN];     // {adv, e^adv, e^{0.2 adv}, exself}
__device__ __align__(16) float g_pt[NN * 128];
__device__ __align__(16) float g_pb[NN * 128];

#define ES_S(v) ((v) >> 17)
#define ES_E(v) ((v) & 0x1FFFF)

// ---------------- kernel 1: relation-weight precompute + per-type degree count ----------------
#define W0_CNT (2 * NN * 32)
#define WL1_CNT (2 * 32 * 64)
#define WL2_CNT (2 * 64 * 64)
#define WL3_CNT (2 * 64 * 32)
#define PRE_CNT (W0_CNT + WL1_CNT + WL2_CNT + WL3_CNT)
#define PRE_BLOCKS (PRE_CNT / 256)
#define CNT_BLOCKS ((EE + 255) / 256)

__global__ void pre_count_kernel(const float* __restrict__ basis0, const float* __restrict__ comp0,
                                 const float* __restrict__ basis1, const float* __restrict__ comp1,
                                 const float* __restrict__ basis2, const float* __restrict__ comp2,
                                 const float* __restrict__ basis3, const float* __restrict__ comp3,
                                 const int* __restrict__ dst, const int* __restrict__ et) {
    int bid = blockIdx.x;
    if (bid >= PRE_BLOCKS) {
        int e = (bid - PRE_BLOCKS) * 256 + threadIdx.x;
        if (e < EE) g_rank[e] = atomicAdd(&g_degT[2 * dst[e] + et[e]], 1);
        return;
    }
    int idx = bid * 256 + threadIdx.x;
    if (idx < W0_CNT) {
        int per = NN * 32;
        int r = idx / per, rem = idx - r * per;
        float v = 0.f;
#pragma unroll
        for (int b = 0; b < 4; b++) v += comp0[r * 4 + b] * basis0[b * per + rem];
        g_W0[idx] = v;
        return;
    }
    idx -= W0_CNT;
    if (idx < WL1_CNT) {
        int per = 32 * 64;
        int r = idx / per, rem = idx - r * per;
        float v = 0.f;
#pragma unroll
        for (int b = 0; b < 4; b++) v += comp1[r * 4 + b] * basis1[b * per + rem];
        g_Wl1[idx] = v;
        return;
    }
    idx -= WL1_CNT;
    if (idx < WL2_CNT) {
        int per = 64 * 64;
        int r = idx / per, rem = idx - r * per;
        float v = 0.f;
#pragma unroll
        for (int b = 0; b < 4; b++) v += comp2[r * 4 + b] * basis2[b * per + rem];
        g_Wl2[idx] = v;
        return;
    }
    idx -= WL2_CNT;
    {
        int per = 64 * 32;
        int r = idx / per, rem = idx - r * per;
        float v = 0.f;
#pragma unroll
        for (int b = 0; b < 4; b++) v += comp3[r * 4 + b] * basis3[b * per + rem];
        g_Wl3[idx] = v;
    }
}

// ---------------- kernel 2: single-pass scan; emits rowptr/mid/inv, re-zeroes degT ----------------
__global__ void scan_kernel() {
    __shared__ int swsum[32];
    int tid = threadIdx.x, lane = tid & 31, wid = tid >> 5;
    int base = tid * 6;
    int d0[6], d1[6];
    int s = 0;
#pragma unroll
    for (int j = 0; j < 6; j++) {
        int i = base + j;
        d0[j] = (i < NN) ? g_degT[2 * i] : 0;
        d1[j] = (i < NN) ? g_degT[2 * i + 1] : 0;
        s += d0[j] + d1[j];
    }
    int x = s;
#pragma unroll
    for (int off = 1; off < 32; off <<= 1) {
        int t = __shfl_up_sync(0xffffffffu, x, off);
        if (lane >= off) x += t;
    }
    if (lane == 31) swsum[wid] = x;
    __syncthreads();
    if (wid == 0) {
        int y = swsum[lane];
#pragma unroll
        for (int off = 1; off < 32; off <<= 1) {
            int t = __shfl_up_sync(0xffffffffu, y, off);
            if (lane >= off) y += t;
        }
        swsum[lane] = y;
    }
    __syncthreads();
    int run = x - s + (wid ? swsum[wid - 1] : 0);
#pragma unroll
    for (int j = 0; j < 6; j++) {
        int i = base + j;
        if (i < NN) {
            g_mid[i] = run + d0[j];
            g_inv[2 * i] = 1.f / fmaxf((float)d0[j], 1.f);
            g_inv[2 * i + 1] = 1.f / fmaxf((float)d1[j], 1.f);
            run += d0[j] + d1[j];
            g_rowptr[i + 1] = run;
            g_degT[2 * i] = 0;
            g_degT[2 * i + 1] = 0;
        }
    }
    if (tid == 0) g_rowptr[0] = 0;
}

// ---------------- kernel 3: atomic-free scatter into type-sorted CSR ----------------
__global__ void scatter_kernel(const int* __restrict__ src, const int* __restrict__ dst,
                               const int* __restrict__ et) {
    int e = blockIdx.x * blockDim.x + threadIdx.x;
    if (e < EE) {
        int d = dst[e], t = et[e];
        int p = (t ? g_mid[d] : g_rowptr[d]) + g_rank[e];
        g_es[p] = e | (src[e] << 17);
    }
}

// ---------------- pipelined two-segment aggregation helper ----------------
template <int W>
__device__ __forceinline__ void agg_seg(const float* __restrict__ plane,
                                        int beg, int mid, int end, int lane,
                                        float& a0, float& a1) {
    const float* p1 = plane + (size_t)NN * W;
    int k = beg;
    if (end - k >= 8) {
        int pv[8];
#pragma unroll
        for (int i = 0; i < 8; i++) pv[i] = g_es[k + i];
        while (k + 16 <= end) {
            int nv[8];
#pragma unroll
            for (int i = 0; i < 8; i++) nv[i] = g_es[k + 8 + i];
#pragma unroll
            for (int i = 0; i < 8; i++) {
                const float* pl = (k + i < mid) ? plane : p1;
                float f = pl[(size_t)ES_S(pv[i]) * W + lane];
                if (k + i < mid) a0 += f; else a1 += f;
            }
#pragma unroll
            for (int i = 0; i < 8; i++) pv[i] = nv[i];
            k += 8;
        }
#pragma unroll
        for (int i = 0; i < 8; i++) {
            const float* pl = (k + i < mid) ? plane : p1;
            float f = pl[(size_t)ES_S(pv[i]) * W + lane];
            if (k + i < mid) a0 += f; else a1 += f;
        }
        k += 8;
    }
    for (; k < end; k++) {
        const float* pl = (k < mid) ? plane : p1;
        float f = pl[(size_t)ES_S(g_es[k]) * W + lane];
        if (k < mid) a0 += f; else a1 += f;
    }
}

// ---------------- kernel 4: layer-0 agg (identity input) + dense1 fused ----------------
__global__ void l0d1_kernel(const float* __restrict__ root0, const float* __restrict__ rbias0,
                            const float* __restrict__ root1, const float* __restrict__ rbias1) {
    __shared__ float sx[8][32];
    int tid = threadIdx.x, w = tid >> 5, lane = tid & 31;
    int node = blockIdx.x * 8 + w;
    {
        int beg = g_rowptr[node], mid = g_mid[node], end = g_rowptr[node + 1];
        float a0 = 0.f, a1 = 0.f;
        agg_seg<32>(g_W0, beg, mid, end, lane, a0, a1);
        float2 iv = *(const float2*)(g_inv + 2 * node);
        float out = root0[node * 32 + lane] + rbias0[lane] + a0 * iv.x + a1 * iv.y;
        sx[w][lane] = tanhf(out);
    }
    __syncthreads();
#pragma unroll
    for (int t = tid; t < 512; t += 256) {
        int ln = t >> 6, o = t & 63;
        int nn = blockIdx.x * 8 + ln;
        float a0 = 0.f, a1 = 0.f, ar = 0.f;
#pragma unroll 8
        for (int i = 0; i < 32; i++) {
            float xv = sx[ln][i];
            a0 += xv * g_Wl1[i * 64 + o];
            a1 += xv * g_Wl1[32 * 64 + i * 64 + o];
            ar += xv * root1[i * 64 + o];
        }
        g_hrA[nn * 64 + o] = a0;
        g_hrA[NN * 64 + nn * 64 + o] = a1;
        g_rootout[nn * 64 + o] = ar + rbias1[o];
    }
}

// ---------------- kernel 5: agg1 + dense2 fused ----------------
__global__ void a1d2_kernel(const float* __restrict__ root2, const float* __restrict__ rbias2) {
    __shared__ float sx[4][64];
    int tid = threadIdx.x;
    int ln = tid >> 6, o = tid & 63;
    int node = blockIdx.x * 4 + ln;
    {
        int beg = g_rowptr[node], mid = g_mid[node], end = g_rowptr[node + 1];
        float a0 = 0.f, a1 = 0.f;
        agg_seg<64>(g_hrA, beg, mid, end, o, a0, a1);
        float2 iv = *(const float2*)(g_inv + 2 * node);
        float out = g_rootout[node * 64 + o] + a0 * iv.x + a1 * iv.y;
        sx[ln][o] = tanhf(out);
    }
    __syncthreads();
    float a0 = 0.f, a1 = 0.f, ar = 0.f;
#pragma unroll 8
    for (int i = 0; i < 64; i++) {
        float xv = sx[ln][i];
        a0 += xv * g_Wl2[i * 64 + o];
        a1 += xv * g_Wl2[64 * 64 + i * 64 + o];
        ar += xv * root2[i * 64 + o];
    }
    g_hrB[node * 64 + o] = a0;
    g_hrB[NN * 64 + node * 64 + o] = a1;
    g_rootout[node * 64 + o] = ar + rbias2[o];
}

// ---------------- kernel 6: agg2 + dense3 fused ----------------
__global__ void a2d3_kernel(const float* __restrict__ root3, const float* __restrict__ rbias3) {
    __shared__ float sx[4][64];
    int tid = threadIdx.x;
    int ln = tid >> 6, o = tid & 63;
    int node = blockIdx.x * 4 + ln;
    {
        int beg = g_rowptr[node], mid = g_mid[node], end = g_rowptr[node + 1];
        float a0 = 0.f, a1 = 0.f;
        agg_seg<64>(g_hrB, beg, mid, end, o, a0, a1);
        float2 iv = *(const float2*)(g_inv + 2 * node);
        float out = g_rootout[node * 64 + o] + a0 * iv.x + a1 * iv.y;
        sx[ln][o] = tanhf(out);
    }
    __syncthreads();
    if (tid < 128) {
        int ln3 = tid >> 5, o3 = tid & 31;
        int nn = blockIdx.x * 4 + ln3;
        float a0 = 0.f, a1 = 0.f, ar = 0.f;
#pragma unroll 8
        for (int i = 0; i < 64; i++) {
            float xv = sx[ln3][i];
            a0 += xv * g_Wl3[i * 32 + o3];
            a1 += xv * g_Wl3[64 * 32 + i * 32 + o3];
            ar += xv * root3[i * 32 + o3];
        }
        g_hrA[nn * 32 + o3] = a0;
        g_hrA[NN * 32 + nn * 32 + o3] = a1;
        g_rootout3[nn * 32 + o3] = ar + rbias3[o3];
    }
}

// ---------------- kernel 7: agg3 + GAT h GEMM + attention-exp precompute, fused ----------------
__global__ void agg3_gath_kernel(const float* __restrict__ gw,
                                 const float* __restrict__ as, const float* __restrict__ ad) {
    __shared__ __align__(16) float sx[16][32];
    __shared__ float s_as[16], s_ad[16];
    int tid = threadIdx.x;  // 512
    int node0 = blockIdx.x * 16;
    int w = tid >> 5, lane = tid & 31;
    {
        int node = node0 + w;
        int beg = g_rowptr[node], mid = g_mid[node], end = g_rowptr[node + 1];
        float a0 = 0.f, a1 = 0.f;
        agg_seg<32>(g_hrA, beg, mid, end, lane, a0, a1);
        float2 iv = *(const float2*)(g_inv + 2 * node);
        float out = g_rootout3[node * 32 + lane] + a0 * iv.x + a1 * iv.y;
        sx[w][lane] = tanhf(out);
    }
    if (tid < 16) { s_as[tid] = 0.f; s_ad[tid] = 0.f; }
    __syncthreads();
    int cg = tid & 127;
    int ng = tid >> 7;
    int col4 = cg * 4;
    int nbase = ng * 4;
    float acc[4][4];
#pragma unroll
    for (int a = 0; a < 4; a++)
#pragma unroll
        for (int b = 0; b < 4; b++) acc[a][b] = 0.f;
#pragma unroll 8
    for (int i = 0; i < 32; i++) {
        float4 wv = *(const float4*)(gw + i * 512 + col4);
        float x0 = sx[nbase + 0][i], x1 = sx[nbase + 1][i];
        float x2 = sx[nbase + 2][i], x3 = sx[nbase + 3][i];
        acc[0][0] += x0 * wv.x; acc[0][1] += x0 * wv.y; acc[0][2] += x0 * wv.z; acc[0][3] += x0 * wv.w;
        acc[1][0] += x1 * wv.x; acc[1][1] += x1 * wv.y; acc[1][2] += x1 * wv.z; acc[1][3] += x1 * wv.w;
        acc[2][0] += x2 * wv.x; acc[2][1] += x2 * wv.y; acc[2][2] += x2 * wv.z; acc[2][3] += x2 * wv.w;
        acc[3][0] += x3 * wv.x; acc[3][1] += x3 * wv.y; acc[3][2] += x3 * wv.z; acc[3][3] += x3 * wv.w;
    }
#pragma unroll
    for (int a = 0; a < 4; a++) {
        int nn = node0 + nbase + a;
        float4 o = make_float4(acc[a][0], acc[a][1], acc[a][2], acc[a][3]);
        *(float4*)(g_h + (size_t)nn * 512 + col4) = o;
    }
    float4 av = *(const float4*)(as + col4);
    float4 dv = *(const float4*)(ad + col4);
#pragma unroll
    for (int a = 0; a < 4; a++) {
        float ps = acc[a][0] * av.x + acc[a][1] * av.y + acc[a][2] * av.z + acc[a][3] * av.w;
        float pd = acc[a][0] * dv.x + acc[a][1] * dv.y + acc[a][2] * dv.z + acc[a][3] * dv.w;
#pragma unroll
        for (int off = 16; off; off >>= 1) {
            ps += __shfl_down_sync(0xffffffffu, ps, off);
            pd += __shfl_down_sync(0xffffffffu, pd, off);
        }
        if (lane == 0) {
            atomicAdd(&s_as[nbase + a], ps);
            atomicAdd(&s_ad[nbase + a], pd);
        }
    }
    __syncthreads();
    if (tid < 16) {
        int nn = node0 + tid;
        float asv = s_as[tid], adv = s_ad[tid];
        float al = asv + adv;
        float exself = expf(al > 0.f ? al : 0.2f * al);
        g_attnS[nn] = make_float4(asv, expf(asv), expf(0.2f * asv), 0.f);
        g_attnD[nn] = make_float4(adv, expf(adv), expf(0.2f * adv), exself);
    }
}

// ---------------- kernel 8: GAT softmax-agg (group/node, staged) + w1 GEMM, fused ----------------
// 32 nodes/block, 512 threads = 4 groups of 128. Each group handles 8 nodes
// sequentially with 64-edge smem staging (named barriers 1..4). GEMM phase:
// 512 threads, thread tile = 4 nodes x 4 cols, w1 read once per 32 nodes.
#define GA_NODES 32
#define GA_SMEM (GA_NODES * 512 * 4)   // 64 KB node tile

__global__ void gatagg_ptpb_kernel(const float* __restrict__ gbias,
                                   const float* __restrict__ w1, const float* __restrict__ b1) {
    extern __shared__ __align__(16) float sx[];  // [32][512]
    __shared__ float sex[4][64];
    __shared__ int ssrc[4][64];
    int tid = threadIdx.x;          // 512
    int node0 = blockIdx.x * GA_NODES;
    int g = tid >> 7;               // group 0..3
    int gtid = tid & 127;
    const float4* h4 = (const float4*)g_h;
    float4 gb4 = ((const float4*)gbias)[gtid];
    // phase A: softmax-aggregate, 8 nodes per group
    for (int kk = 0; kk < 8; kk++) {
        int local = g * 8 + kk;
        int n = node0 + local;
        if (n < NN) {
            float4 adn = g_attnD[n];
            float advn = adn.x, F1 = adn.y, F2 = adn.z, exself = adn.w;
            int beg = g_rowptr[n], deg = g_rowptr[n + 1] - beg;
            float4 hs = h4[(size_t)n * 128 + gtid];
            float ax = exself * hs.x, ay = exself * hs.y, az = exself * hs.z, aw = exself * hs.w;
            float dsum = exself;
            for (int base = 0; base < deg; base += 64) {
                int cnt = min(64, deg - base);
                if (gtid < cnt) {
                    int v = g_es[beg + base + gtid];
                    int s = ES_S(v);
                    ssrc[g][gtid] = s;
                    float4 A = g_attnS[s];
                    sex[g][gtid] = (A.x + advn > 0.f) ? A.y * F1 : A.z * F2;
                }
                asm volatile("bar.sync %0, %1;" :: "r"(g + 1), "r"(128) : "memory");
                int j = 0;
                for (; j + 2 <= cnt; j += 2) {
                    float e0 = sex[g][j], e1 = sex[g][j + 1];
                    float4 h0 = h4[(size_t)ssrc[g][j] * 128 + gtid];
                    float4 h1 = h4[(size_t)ssrc[g][j + 1] * 128 + gtid];
                    ax += e0 * h0.x + e1 * h1.x;
                    ay += e0 * h0.y + e1 * h1.y;
                    az += e0 * h0.z + e1 * h1.z;
                    aw += e0 * h0.w + e1 * h1.w;
                    dsum += e0 + e1;
                }
                if (j < cnt) {
                    float e0 = sex[g][j];
                    float4 h0 = h4[(size_t)ssrc[g][j] * 128 + gtid];
                    ax += e0 * h0.x; ay += e0 * h0.y; az += e0 * h0.z; aw += e0 * h0.w;
                    dsum += e0;
                }
                asm volatile("bar.sync %0, %1;" :: "r"(g + 1), "r"(128) : "memory");
            }
            float inv = 1.f / fmaxf(dsum, 1e-16f);
            float4 o = make_float4(fmaxf(ax * inv + gb4.x, 0.f), fmaxf(ay * inv + gb4.y, 0.f),
                                   fmaxf(az * inv + gb4.z, 0.f), fmaxf(aw * inv + gb4.w, 0.f));
            ((float4*)(sx + local * 512))[gtid] = o;
        }
    }
    __syncthreads();
    // phase B: GEMM 1024->256 split as two 512-col halves over 32 nodes
    int cg = tid & 63, ng = tid >> 6;         // 64 col groups x 8 node groups
    int half = cg >> 5, col4 = (cg & 31) * 4;
    const float* wp = w1 + (half ? 512 * 128 : 0) + col4;
    int nbase = ng * 4;
    const float* r0 = sx + (nbase + 0) * 512;
    const float* r1 = sx + (nbase + 1) * 512;
    const float* r2 = sx + (nbase + 2) * 512;
    const float* r3 = sx + (nbase + 3) * 512;
    float acc[4][4];
#pragma unroll
    for (int a = 0; a < 4; a++)
#pragma unroll
        for (int b = 0; b < 4; b++) acc[a][b] = 0.f;
#pragma unroll 4
    for (int i = 0; i < 512; i++) {
        float4 wv = *(const float4*)(wp + i * 128);
        float x0 = r0[i], x1 = r1[i], x2 = r2[i], x3 = r3[i];
        acc[0][0] += x0 * wv.x; acc[0][1] += x0 * wv.y; acc[0][2] += x0 * wv.z; acc[0][3] += x0 * wv.w;
        acc[1][0] += x1 * wv.x; acc[1][1] += x1 * wv.y; acc[1][2] += x1 * wv.z; acc[1][3] += x1 * wv.w;
        acc[2][0] += x2 * wv.x; acc[2][1] += x2 * wv.y; acc[2][2] += x2 * wv.z; acc[2][3] += x2 * wv.w;
        acc[3][0] += x3 * wv.x; acc[3][1] += x3 * wv.y; acc[3][2] += x3 * wv.z; acc[3][3] += x3 * wv.w;
    }
    float4 bb = half ? make_float4(0.f, 0.f, 0.f, 0.f) : *(const float4*)(b1 + col4);
    float* obase = half ? g_pb : g_pt;
#pragma unroll
    for (int a = 0; a < 4; a++) {
        int nn = node0 + nbase + a;
        if (nn < NN) {
            float4 o = make_float4(acc[a][0] + bb.x, acc[a][1] + bb.y,
                                   acc[a][2] + bb.z, acc[a][3] + bb.w);
            *(float4*)(obase + (size_t)nn * 128 + col4) = o;
        }
    }
}

// ---------------- kernel 9: per-edge output, CSR order ----------------
__global__ void edge_out_kernel(const float* __restrict__ w2, const float* __restrict__ b2,
                                float* __restrict__ out) {
    int tid = threadIdx.x, w = tid >> 5, lane = tid & 31;
    int node = blockIdx.x * 8 + w;
    int beg = g_rowptr[node], end = g_rowptr[node + 1];
    if (beg == end) return;
    const float4* pt4 = (const float4*)g_pt;
    float4 pbv = ((const float4*)g_pb)[(size_t)node * 32 + lane];
    float4 wv = ((const float4*)w2)[lane];
    float bias = b2[0];
    int k = beg;
    for (; k + 2 <= end; k += 2) {
        int v0 = g_es[k], v1 = g_es[k + 1];
        float4 a0 = pt4[(size_t)ES_S(v0) * 32 + lane];
        float4 a1 = pt4[(size_t)ES_S(v1) * 32 + lane];
        float r0 = fmaxf(a0.x + pbv.x, 0.f) * wv.x + fmaxf(a0.y + pbv.y, 0.f) * wv.y
                 + fmaxf(a0.z + pbv.z, 0.f) * wv.z + fmaxf(a0.w + pbv.w, 0.f) * wv.w;
        float r1 = fmaxf(a1.x + pbv.x, 0.f) * wv.x + fmaxf(a1.y + pbv.y, 0.f) * wv.y
                 + fmaxf(a1.z + pbv.z, 0.f) * wv.z + fmaxf(a1.w + pbv.w, 0.f) * wv.w;
#pragma unroll
        for (int off = 16; off; off >>= 1) {
            r0 += __shfl_down_sync(0xffffffffu, r0, off);
            r1 += __shfl_down_sync(0xffffffffu, r1, off);
        }
        if (lane == 0) {
            out[ES_E(v0)] = 1.f / (1.f + expf(-(r0 + bias)));
            out[ES_E(v1)] = 1.f / (1.f + expf(-(r1 + bias)));
        }
    }
    if (k < end) {
        int v = g_es[k];
        float4 a = pt4[(size_t)ES_S(v) * 32 + lane];
        float r = fmaxf(a.x + pbv.x, 0.f) * wv.x + fmaxf(a.y + pbv.y, 0.f) * wv.y
                + fmaxf(a.z + pbv.z, 0.f) * wv.z + fmaxf(a.w + pbv.w, 0.f) * wv.w;
#pragma unroll
        for (int off = 16; off; off >>= 1) r += __shfl_down_sync(0xffffffffu, r, off);
        if (lane == 0) out[ES_E(v)] = 1.f / (1.f + expf(-(r + bias)));
    }
}

// ---------------- launch ----------------
extern "C" void kernel_launch(void* const* d_in, const int* in_sizes, int n_in,
                              void* d_out, int out_size) {
    int off, iE, iT;
    if (in_sizes[0] == 2 * EE) { off = 2; iE = 0; iT = 1; }
    else                       { off = 0; iE = 24; iT = 25; }
    const int* ei = (const int*)d_in[iE];
    const int* et = (const int*)d_in[iT];
    const int* src = ei;
    const int* dst = ei + EE;
    const float* basis0 = (const float*)d_in[off + 0];
    const float* comp0  = (const float*)d_in[off + 1];
    const float* root0  = (const float*)d_in[off + 2];
    const float* rbias0 = (const float*)d_in[off + 3];
    const float* basis1 = (const float*)d_in[off + 4];
    const float* comp1  = (const float*)d_in[off + 5];
    const float* root1  = (const float*)d_in[off + 6];
    const float* rbias1 = (const float*)d_in[off + 7];
    const float* basis2 = (const float*)d_in[off + 8];
    const float* comp2  = (const float*)d_in[off + 9];
    const float* root2  = (const float*)d_in[off + 10];
    const float* rbias2 = (const float*)d_in[off + 11];
    const float* basis3 = (const float*)d_in[off + 12];
    const float* comp3  = (const float*)d_in[off + 13];
    const float* root3  = (const float*)d_in[off + 14];
    const float* rbias3 = (const float*)d_in[off + 15];
    const float* gw  = (const float*)d_in[off + 16];
    const float* gas = (const float*)d_in[off + 17];
    const float* gad = (const float*)d_in[off + 18];
    const float* gb  = (const float*)d_in[off + 19];
    const float* w1  = (const float*)d_in[off + 20];
    const float* b1  = (const float*)d_in[off + 21];
    const float* w2  = (const float*)d_in[off + 22];
    const float* b2  = (const float*)d_in[off + 23];
    float* out = (float*)d_out;

    cudaFuncSetAttribute(gatagg_ptpb_kernel,
                         cudaFuncAttributeMaxDynamicSharedMemorySize, GA_SMEM);

    pre_count_kernel<<<PRE_BLOCKS + CNT_BLOCKS, 256>>>(basis0, comp0, basis1, comp1,
                                                       basis2, comp2, basis3, comp3, dst, et);
    scan_kernel<<<1, 1024>>>();
    scatter_kernel<<<CNT_BLOCKS, 256>>>(src, dst, et);

    l0d1_kernel<<<NN / 8, 256>>>(root0, rbias0, root1, rbias1);
    a1d2_kernel<<<NN / 4, 256>>>(root2, rbias2);
    a2d3_kernel<<<NN / 4, 256>>>(root3, rbias3);

    agg3_gath_kernel<<<NN / 16, 512>>>(gw, gas, gad);
    gatagg_ptpb_kernel<<<(NN + GA_NODES - 1) / GA_NODES, 512, GA_SMEM>>>(gb, w1, b1);
    edge_out_kernel<<<NN / 8, 256>>>(w2, b2, out);
}

// round 9
// speedup vs baseline: 1.1885x; 1.1622x over previous
#include <cuda_runtime.h>
#include <cuda_fp16.h>
#include <math.h>

#define NN 6000
#define EE 100000

// ---------------- device scratch (static, no allocation) ----------------
__device__ int g_deg[NN];          // zeroed at end of scan_kernel each launch (starts zeroed)
__device__ int g_rowptr[NN + 1];
__device__ int g_rank[EE];
__device__ int g_es[EE];           // packed per CSR slot: e | (src<<17) | (type<<30)

__device__ __align__(16) float g_W0[2 * NN * 32];
__device__ __align__(16) float g_Wl1[2 * 32 * 64];
__device__ __align__(16) float g_Wl2[2 * 64 * 64];
__device__ __align__(16) float g_Wl3[2 * 64 * 32];
__device__ __align__(16) float g_hrA[2 * NN * 64];   // layers 1 (64-wide) and 3 (32-wide)
__device__ __align__(16) float g_hrB[2 * NN * 64];   // layer 2 (64-wide)
__device__ __align__(16) float g_rootout[NN * 64];   // layers 1,2
__device__ __align__(16) float g_rootout3[NN * 32];  // layer 3
__device__ __align__(16) __half g_hh[NN * 512];      // GAT hidden (fp16 to halve L2 traffic)
__device__ float g_asv[NN], g_adv[NN];
__device__ __align__(16) float g_pt[NN * 128];       // gat_out @ w1[0:512] (+ b1)
__device__ __align__(16) float g_pb[NN * 128];       // gat_out @ w1[512:1024]

__device__ __forceinline__ float lrelu(float v) { return v > 0.f ? v : 0.2f * v; }

// load 4 consecutive halves as float4
__device__ __forceinline__ float4 ldh4(const uint2* base, size_t idx) {
    uint2 u = base[idx];
    __half2 p0 = *reinterpret_cast<__half2*>(&u.x);
    __half2 p1 = *reinterpret_cast<__half2*>(&u.y);
    float2 f0 = __half22float2(p0);
    float2 f1 = __half22float2(p1);
    return make_float4(f0.x, f0.y, f1.x, f1.y);
}

// ---------------- kernel 1: relation-weight precompute + degree count (fused) ----------------
#define W0_CNT (2 * NN * 32)
#define WL1_CNT (2 * 32 * 64)
#define WL2_CNT (2 * 64 * 64)
#define WL3_CNT (2 * 64 * 32)
#define PRE_CNT (W0_CNT + WL1_CNT + WL2_CNT + WL3_CNT)
#define PRE_BLOCKS (PRE_CNT / 256)              // exact
#define CNT_BLOCKS ((EE + 255) / 256)

__global__ void pre_count_kernel(const float* __restrict__ basis0, const float* __restrict__ comp0,
                                 const float* __restrict__ basis1, const float* __restrict__ comp1,
                                 const float* __restrict__ basis2, const float* __restrict__ comp2,
                                 const float* __restrict__ basis3, const float* __restrict__ comp3,
                                 const int* __restrict__ dst) {
    int bid = blockIdx.x;
    if (bid >= PRE_BLOCKS) {
        int e = (bid - PRE_BLOCKS) * 256 + threadIdx.x;
        if (e < EE) g_rank[e] = atomicAdd(&g_deg[dst[e]], 1);
        return;
    }
    int idx = bid * 256 + threadIdx.x;
    if (idx < W0_CNT) {
        int per = NN * 32;
        int r = idx / per, rem = idx - r * per;
        float v = 0.f;
#pragma unroll
        for (int b = 0; b < 4; b++) v += comp0[r * 4 + b] * basis0[b * per + rem];
        g_W0[idx] = v;
        return;
    }
    idx -= W0_CNT;
    if (idx < WL1_CNT) {
        int per = 32 * 64;
        int r = idx / per, rem = idx - r * per;
        float v = 0.f;
#pragma unroll
        for (int b = 0; b < 4; b++) v += comp1[r * 4 + b] * basis1[b * per + rem];
        g_Wl1[idx] = v;
        return;
    }
    idx -= WL1_CNT;
    if (idx < WL2_CNT) {
        int per = 64 * 64;
        int r = idx / per, rem = idx - r * per;
        float v = 0.f;
#pragma unroll
        for (int b = 0; b < 4; b++) v += comp2[r * 4 + b] * basis2[b * per + rem];
        g_Wl2[idx] = v;
        return;
    }
    idx -= WL2_CNT;
    {
        int per = 64 * 32;
        int r = idx / per, rem = idx - r * per;
        float v = 0.f;
#pragma unroll
        for (int b = 0; b < 4; b++) v += comp3[r * 4 + b] * basis3[b * per + rem];
        g_Wl3[idx] = v;
    }
}

// ---------------- kernel 2: single-pass scan (also re-zeroes deg for next launch) ----------------
__global__ void scan_kernel() {
    __shared__ int swsum[32];
    int tid = threadIdx.x, lane = tid & 31, wid = tid >> 5;
    int base = tid * 6;
    int v[6];
    int s = 0;
#pragma unroll
    for (int j = 0; j < 6; j++) {
        int i = base + j;
        v[j] = (i < NN) ? g_deg[i] : 0;
        s += v[j];
    }
    int x = s;
#pragma unroll
    for (int off = 1; off < 32; off <<= 1) {
        int t = __shfl_up_sync(0xffffffffu, x, off);
        if (lane >= off) x += t;
    }
    if (lane == 31) swsum[wid] = x;
    __syncthreads();
    if (wid == 0) {
        int y = swsum[lane];
#pragma unroll
        for (int off = 1; off < 32; off <<= 1) {
            int t = __shfl_up_sync(0xffffffffu, y, off);
            if (lane >= off) y += t;
        }
        swsum[lane] = y;
    }
    __syncthreads();
    int run = x - s + (wid ? swsum[wid - 1] : 0);
#pragma unroll
    for (int j = 0; j < 6; j++) {
        int i = base + j;
        run += v[j];
        if (i < NN) g_rowptr[i + 1] = run;
    }
    if (tid == 0) g_rowptr[0] = 0;
#pragma unroll
    for (int j = 0; j < 6; j++) {
        int i = base + j;
        if (i < NN) g_deg[i] = 0;   // restore invariant for next launch
    }
}

// ---------------- kernel 3: atomic-free scatter, packed slot ----------------
__global__ void scatter_kernel(const int* __restrict__ src, const int* __restrict__ dst,
                               const int* __restrict__ et) {
    int e = blockIdx.x * blockDim.x + threadIdx.x;
    if (e < EE) {
        int p = g_rowptr[dst[e]] + g_rank[e];
        g_es[p] = e | (src[e] << 17) | (et[e] << 30);
    }
}

#define ES_S(v) (((v) >> 17) & 0x1FFF)
#define ES_T(v) (((v) >> 30) & 1)
#define ES_E(v) ((v) & 0x1FFFF)

// ---------------- kernel 4: layer-0 agg (identity input) + dense1 fused ----------------
__global__ void l0d1_kernel(const float* __restrict__ root0, const float* __restrict__ rbias0,
                            const float* __restrict__ root1, const float* __restrict__ rbias1) {
    __shared__ float sx[8][32];
    int tid = threadIdx.x, w = tid >> 5, lane = tid & 31;
    int node = blockIdx.x * 8 + w;
    {
        int beg = g_rowptr[node], end = g_rowptr[node + 1];
        float a0 = 0.f, a1 = 0.f, c0 = 0.f, c1 = 0.f;
        int k = beg;
        for (; k + 4 <= end; k += 4) {
            int v0 = g_es[k], v1 = g_es[k + 1], v2 = g_es[k + 2], v3 = g_es[k + 3];
            float f0 = g_W0[ES_T(v0) * (NN * 32) + ES_S(v0) * 32 + lane];
            float f1 = g_W0[ES_T(v1) * (NN * 32) + ES_S(v1) * 32 + lane];
            float f2 = g_W0[ES_T(v2) * (NN * 32) + ES_S(v2) * 32 + lane];
            float f3 = g_W0[ES_T(v3) * (NN * 32) + ES_S(v3) * 32 + lane];
            if (ES_T(v0)) { a1 += f0; c1 += 1.f; } else { a0 += f0; c0 += 1.f; }
            if (ES_T(v1)) { a1 += f1; c1 += 1.f; } else { a0 += f1; c0 += 1.f; }
            if (ES_T(v2)) { a1 += f2; c1 += 1.f; } else { a0 += f2; c0 += 1.f; }
            if (ES_T(v3)) { a1 += f3; c1 += 1.f; } else { a0 += f3; c0 += 1.f; }
        }
        for (; k < end; k++) {
            int v = g_es[k];
            float f = g_W0[ES_T(v) * (NN * 32) + ES_S(v) * 32 + lane];
            if (ES_T(v)) { a1 += f; c1 += 1.f; } else { a0 += f; c0 += 1.f; }
        }
        float out = root0[node * 32 + lane] + rbias0[lane]
                  + a0 / fmaxf(c0, 1.f) + a1 / fmaxf(c1, 1.f);
        sx[w][lane] = tanhf(out);
    }
    __syncthreads();
#pragma unroll
    for (int t = tid; t < 512; t += 256) {
        int ln = t >> 6, o = t & 63;
        int nn = blockIdx.x * 8 + ln;
        float a0 = 0.f, a1 = 0.f, ar = 0.f;
#pragma unroll 8
        for (int i = 0; i < 32; i++) {
            float xv = sx[ln][i];
            a0 += xv * g_Wl1[i * 64 + o];
            a1 += xv * g_Wl1[32 * 64 + i * 64 + o];
            ar += xv * root1[i * 64 + o];
        }
        g_hrA[nn * 64 + o] = a0;
        g_hrA[NN * 64 + nn * 64 + o] = a1;
        g_rootout[nn * 64 + o] = ar + rbias1[o];
    }
}

// ---------------- kernel 5: agg1 + dense2 fused ----------------
__global__ void a1d2_kernel(const float* __restrict__ root2, const float* __restrict__ rbias2) {
    __shared__ float sx[4][64];
    int tid = threadIdx.x;
    int ln = tid >> 6, o = tid & 63;
    int node = blockIdx.x * 4 + ln;
    {
        int beg = g_rowptr[node], end = g_rowptr[node + 1];
        float a0 = 0.f, a1 = 0.f, c0 = 0.f, c1 = 0.f;
        int k = beg;
        for (; k + 4 <= end; k += 4) {
            int v0 = g_es[k], v1 = g_es[k + 1], v2 = g_es[k + 2], v3 = g_es[k + 3];
            float f0 = g_hrA[ES_T(v0) * (NN * 64) + ES_S(v0) * 64 + o];
            float f1 = g_hrA[ES_T(v1) * (NN * 64) + ES_S(v1) * 64 + o];
            float f2 = g_hrA[ES_T(v2) * (NN * 64) + ES_S(v2) * 64 + o];
            float f3 = g_hrA[ES_T(v3) * (NN * 64) + ES_S(v3) * 64 + o];
            if (ES_T(v0)) { a1 += f0; c1 += 1.f; } else { a0 += f0; c0 += 1.f; }
            if (ES_T(v1)) { a1 += f1; c1 += 1.f; } else { a0 += f1; c0 += 1.f; }
            if (ES_T(v2)) { a1 += f2; c1 += 1.f; } else { a0 += f2; c0 += 1.f; }
            if (ES_T(v3)) { a1 += f3; c1 += 1.f; } else { a0 += f3; c0 += 1.f; }
        }
        for (; k < end; k++) {
            int v = g_es[k];
            float f = g_hrA[ES_T(v) * (NN * 64) + ES_S(v) * 64 + o];
            if (ES_T(v)) { a1 += f; c1 += 1.f; } else { a0 += f; c0 += 1.f; }
        }
        float out = g_rootout[node * 64 + o] + a0 / fmaxf(c0, 1.f) + a1 / fmaxf(c1, 1.f);
        sx[ln][o] = tanhf(out);
    }
    __syncthreads();
    float a0 = 0.f, a1 = 0.f, ar = 0.f;
#pragma unroll 8
    for (int i = 0; i < 64; i++) {
        float xv = sx[ln][i];
        a0 += xv * g_Wl2[i * 64 + o];
        a1 += xv * g_Wl2[64 * 64 + i * 64 + o];
        ar += xv * root2[i * 64 + o];
    }
    g_hrB[node * 64 + o] = a0;
    g_hrB[NN * 64 + node * 64 + o] = a1;
    g_rootout[node * 64 + o] = ar + rbias2[o];
}

// ---------------- kernel 6: agg2 + dense3 fused ----------------
__global__ void a2d3_kernel(const float* __restrict__ root3, const float* __restrict__ rbias3) {
    __shared__ float sx[4][64];
    int tid = threadIdx.x;
    int ln = tid >> 6, o = tid & 63;
    int node = blockIdx.x * 4 + ln;
    {
        int beg = g_rowptr[node], end = g_rowptr[node + 1];
        float a0 = 0.f, a1 = 0.f, c0 = 0.f, c1 = 0.f;
        int k = beg;
        for (; k + 4 <= end; k += 4) {
            int v0 = g_es[k], v1 = g_es[k + 1], v2 = g_es[k + 2], v3 = g_es[k + 3];
            float f0 = g_hrB[ES_T(v0) * (NN * 64) + ES_S(v0) * 64 + o];
            float f1 = g_hrB[ES_T(v1) * (NN * 64) + ES_S(v1) * 64 + o];
            float f2 = g_hrB[ES_T(v2) * (NN * 64) + ES_S(v2) * 64 + o];
            float f3 = g_hrB[ES_T(v3) * (NN * 64) + ES_S(v3) * 64 + o];
            if (ES_T(v0)) { a1 += f0; c1 += 1.f; } else { a0 += f0; c0 += 1.f; }
            if (ES_T(v1)) { a1 += f1; c1 += 1.f; } else { a0 += f1; c0 += 1.f; }
            if (ES_T(v2)) { a1 += f2; c1 += 1.f; } else { a0 += f2; c0 += 1.f; }
            if (ES_T(v3)) { a1 += f3; c1 += 1.f; } else { a0 += f3; c0 += 1.f; }
        }
        for (; k < end; k++) {
            int v = g_es[k];
            float f = g_hrB[ES_T(v) * (NN * 64) + ES_S(v) * 64 + o];
            if (ES_T(v)) { a1 += f; c1 += 1.f; } else { a0 += f; c0 += 1.f; }
        }
        float out = g_rootout[node * 64 + o] + a0 / fmaxf(c0, 1.f) + a1 / fmaxf(c1, 1.f);
        sx[ln][o] = tanhf(out);
    }
    __syncthreads();
    if (tid < 128) {
        int ln3 = tid >> 5, o3 = tid & 31;
        int nn = blockIdx.x * 4 + ln3;
        float a0 = 0.f, a1 = 0.f, ar = 0.f;
#pragma unroll 8
        for (int i = 0; i < 64; i++) {
            float xv = sx[ln3][i];
            a0 += xv * g_Wl3[i * 32 + o3];
            a1 += xv * g_Wl3[64 * 32 + i * 32 + o3];
            ar += xv * root3[i * 32 + o3];
        }
        g_hrA[nn * 32 + o3] = a0;
        g_hrA[NN * 32 + nn * 32 + o3] = a1;
        g_rootout3[nn * 32 + o3] = ar + rbias3[o3];
    }
}

// ---------------- kernel 7: agg3 + GAT h GEMM + asv/adv, fused (h stored fp16) ----------------
__global__ void agg3_gath_kernel(const float* __restrict__ gw,
                                 const float* __restrict__ as, const float* __restrict__ ad) {
    __shared__ __align__(16) float sx[16][32];
    __shared__ float s_as[16], s_ad[16];
    int tid = threadIdx.x;  // 512
    int node0 = blockIdx.x * 16;
    int w = tid >> 5, lane = tid & 31;
    // phase 0: agg3, warp per node
    {
        int node = node0 + w;
        int beg = g_rowptr[node], end = g_rowptr[node + 1];
        float a0 = 0.f, a1 = 0.f, c0 = 0.f, c1 = 0.f;
        int k = beg;
        for (; k + 4 <= end; k += 4) {
            int v0 = g_es[k], v1 = g_es[k + 1], v2 = g_es[k + 2], v3 = g_es[k + 3];
            float f0 = g_hrA[ES_T(v0) * (NN * 32) + ES_S(v0) * 32 + lane];
            float f1 = g_hrA[ES_T(v1) * (NN * 32) + ES_S(v1) * 32 + lane];
            float f2 = g_hrA[ES_T(v2) * (NN * 32) + ES_S(v2) * 32 + lane];
            float f3 = g_hrA[ES_T(v3) * (NN * 32) + ES_S(v3) * 32 + lane];
            if (ES_T(v0)) { a1 += f0; c1 += 1.f; } else { a0 += f0; c0 += 1.f; }
            if (ES_T(v1)) { a1 += f1; c1 += 1.f; } else { a0 += f1; c0 += 1.f; }
            if (ES_T(v2)) { a1 += f2; c1 += 1.f; } else { a0 += f2; c0 += 1.f; }
            if (ES_T(v3)) { a1 += f3; c1 += 1.f; } else { a0 += f3; c0 += 1.f; }
        }
        for (; k < end; k++) {
            int v = g_es[k];
            float f = g_hrA[ES_T(v) * (NN * 32) + ES_S(v) * 32 + lane];
            if (ES_T(v)) { a1 += f; c1 += 1.f; } else { a0 += f; c0 += 1.f; }
        }
        float out = g_rootout3[node * 32 + lane] + a0 / fmaxf(c0, 1.f) + a1 / fmaxf(c1, 1.f);
        sx[w][lane] = tanhf(out);
    }
    if (tid < 16) { s_as[tid] = 0.f; s_ad[tid] = 0.f; }
    __syncthreads();
    // phase 1: GEMM 32 -> 512 with fused attention-logit dots
    int cg = tid & 127;
    int ng = tid >> 7;
    int col4 = cg * 4;
    int nbase = ng * 4;
    float acc[4][4];
#pragma unroll
    for (int a = 0; a < 4; a++)
#pragma unroll
        for (int b = 0; b < 4; b++) acc[a][b] = 0.f;
#pragma unroll 8
    for (int i = 0; i < 32; i++) {
        float4 wv = *(const float4*)(gw + i * 512 + col4);
        float x0 = sx[nbase + 0][i], x1 = sx[nbase + 1][i];
        float x2 = sx[nbase + 2][i], x3 = sx[nbase + 3][i];
        acc[0][0] += x0 * wv.x; acc[0][1] += x0 * wv.y; acc[0][2] += x0 * wv.z; acc[0][3] += x0 * wv.w;
        acc[1][0] += x1 * wv.x; acc[1][1] += x1 * wv.y; acc[1][2] += x1 * wv.z; acc[1][3] += x1 * wv.w;
        acc[2][0] += x2 * wv.x; acc[2][1] += x2 * wv.y; acc[2][2] += x2 * wv.z; acc[2][3] += x2 * wv.w;
        acc[3][0] += x3 * wv.x; acc[3][1] += x3 * wv.y; acc[3][2] += x3 * wv.z; acc[3][3] += x3 * wv.w;
    }
#pragma unroll
    for (int a = 0; a < 4; a++) {
        int nn = node0 + nbase + a;
        __half2 h0 = __floats2half2_rn(acc[a][0], acc[a][1]);
        __half2 h1 = __floats2half2_rn(acc[a][2], acc[a][3]);
        uint2 u;
        u.x = *reinterpret_cast<unsigned*>(&h0);
        u.y = *reinterpret_cast<unsigned*>(&h1);
        *reinterpret_cast<uint2*>(g_hh + (size_t)nn * 512 + col4) = u;
    }
    float4 av = *(const float4*)(as + col4);
    float4 dv = *(const float4*)(ad + col4);
#pragma unroll
    for (int a = 0; a < 4; a++) {
        float ps = acc[a][0] * av.x + acc[a][1] * av.y + acc[a][2] * av.z + acc[a][3] * av.w;
        float pd = acc[a][0] * dv.x + acc[a][1] * dv.y + acc[a][2] * dv.z + acc[a][3] * dv.w;
#pragma unroll
        for (int off = 16; off; off >>= 1) {
            ps += __shfl_down_sync(0xffffffffu, ps, off);
            pd += __shfl_down_sync(0xffffffffu, pd, off);
        }
        if (lane == 0) {
            atomicAdd(&s_as[nbase + a], ps);
            atomicAdd(&s_ad[nbase + a], pd);
        }
    }
    __syncthreads();
    if (tid < 16) {
        int nn = node0 + tid;
        g_asv[nn] = s_as[tid];
        g_adv[nn] = s_ad[tid];
    }
}

// ---------------- kernel 8: GAT softmax-agg + edge-MLP node projection, fused ----------------
// 16 nodes/block, 256 threads = 2 groups of 128 (4 warps each, named barriers 1/2).
__global__ void gatagg_ptpb_kernel(const float* __restrict__ gbias,
                                   const float* __restrict__ w1, const float* __restrict__ b1) {
    __shared__ __align__(16) float sx[16][512];
    __shared__ float sex[2][64];
    __shared__ int ssrc[2][64];
    int tid = threadIdx.x;
    int node0 = blockIdx.x * 16;
    int g = tid >> 7;
    int gtid = tid & 127;
    const uint2* h2 = (const uint2*)g_hh;   // 4 halves per uint2
    float4 gb4 = ((const float4*)gbias)[gtid];
    for (int k = 0; k < 8; k++) {
        int n = node0 + g * 8 + k;
        int beg = g_rowptr[n], deg = g_rowptr[n + 1] - beg;
        float advn = g_adv[n];
        float exself = expf(lrelu(g_asv[n] + advn));
        float4 hs = ldh4(h2, (size_t)n * 128 + gtid);
        float ax = exself * hs.x, ay = exself * hs.y, az = exself * hs.z, aw = exself * hs.w;
        float dsum = exself;
        for (int base = 0; base < deg; base += 64) {
            int cnt = min(64, deg - base);
            if (gtid < cnt) {
                int v = g_es[beg + base + gtid];
                int s = ES_S(v);
                ssrc[g][gtid] = s;
                sex[g][gtid] = expf(lrelu(g_asv[s] + advn));
            }
            asm volatile("bar.sync %0, %1;" :: "r"(g + 1), "r"(128) : "memory");
            for (int j = 0; j < cnt; j++) {
                float exv = sex[g][j];
                float4 hv = ldh4(h2, (size_t)ssrc[g][j] * 128 + gtid);
                ax += exv * hv.x; ay += exv * hv.y; az += exv * hv.z; aw += exv * hv.w;
                dsum += exv;
            }
            asm volatile("bar.sync %0, %1;" :: "r"(g + 1), "r"(128) : "memory");
        }
        float inv = 1.f / fmaxf(dsum, 1e-16f);
        float4 o = make_float4(fmaxf(ax * inv + gb4.x, 0.f), fmaxf(ay * inv + gb4.y, 0.f),
                               fmaxf(az * inv + gb4.z, 0.f), fmaxf(aw * inv + gb4.w, 0.f));
        ((float4*)sx[g * 8 + k])[gtid] = o;
    }
    __syncthreads();
    // GEMM phase: 1024 -> 256 projection split as two 512-col halves
    int cg = tid & 63;
    int ng = tid >> 6;
    int half = cg >> 5;
    int col4 = (cg & 31) * 4;
    const float* wp = w1 + (half ? 512 * 128 : 0) + col4;
    int nbase = ng * 4;
    float acc[4][4];
#pragma unroll
    for (int a = 0; a < 4; a++)
#pragma unroll
        for (int b = 0; b < 4; b++) acc[a][b] = 0.f;
#pragma unroll 4
    for (int i = 0; i < 512; i++) {
        float4 wv = *(const float4*)(wp + i * 128);
        float x0 = sx[nbase + 0][i], x1 = sx[nbase + 1][i];
        float x2 = sx[nbase + 2][i], x3 = sx[nbase + 3][i];
        acc[0][0] += x0 * wv.x; acc[0][1] += x0 * wv.y; acc[0][2] += x0 * wv.z; acc[0][3] += x0 * wv.w;
        acc[1][0] += x1 * wv.x; acc[1][1] += x1 * wv.y; acc[1][2] += x1 * wv.z; acc[1][3] += x1 * wv.w;
        acc[2][0] += x2 * wv.x; acc[2][1] += x2 * wv.y; acc[2][2] += x2 * wv.z; acc[2][3] += x2 * wv.w;
        acc[3][0] += x3 * wv.x; acc[3][1] += x3 * wv.y; acc[3][2] += x3 * wv.z; acc[3][3] += x3 * wv.w;
    }
    float4 bb = half ? make_float4(0.f, 0.f, 0.f, 0.f) : *(const float4*)(b1 + col4);
    float* obase = half ? g_pb : g_pt;
#pragma unroll
    for (int a = 0; a < 4; a++) {
        int nn = node0 + nbase + a;
        float4 o = make_float4(acc[a][0] + bb.x, acc[a][1] + bb.y,
                               acc[a][2] + bb.z, acc[a][3] + bb.w);
        *(float4*)(obase + (size_t)nn * 128 + col4) = o;
    }
}

// ---------------- kernel 9: per-edge output, CSR order (pb[dst] loaded once/warp) ----------------
__global__ void edge_out_kernel(const float* __restrict__ w2, const float* __restrict__ b2,
                                float* __restrict__ out) {
    int tid = threadIdx.x, w = tid >> 5, lane = tid & 31;
    int node = blockIdx.x * 8 + w;
    int beg = g_rowptr[node], end = g_rowptr[node + 1];
    if (beg == end) return;
    const float4* pt4 = (const float4*)g_pt;
    float4 pbv = ((const float4*)g_pb)[(size_t)node * 32 + lane];
    float4 wv = ((const float4*)w2)[lane];
    float bias = b2[0];
    int k = beg;
    for (; k + 2 <= end; k += 2) {
        int v0 = g_es[k], v1 = g_es[k + 1];
        float4 a0 = pt4[(size_t)ES_S(v0) * 32 + lane];
        float4 a1 = pt4[(size_t)ES_S(v1) * 32 + lane];
        float r0 = fmaxf(a0.x + pbv.x, 0.f) * wv.x + fmaxf(a0.y + pbv.y, 0.f) * wv.y
                 + fmaxf(a0.z + pbv.z, 0.f) * wv.z + fmaxf(a0.w + pbv.w, 0.f) * wv.w;
        float r1 = fmaxf(a1.x + pbv.x, 0.f) * wv.x + fmaxf(a1.y + pbv.y, 0.f) * wv.y
                 + fmaxf(a1.z + pbv.z, 0.f) * wv.z + fmaxf(a1.w + pbv.w, 0.f) * wv.w;
#pragma unroll
        for (int off = 16; off; off >>= 1) {
            r0 += __shfl_down_sync(0xffffffffu, r0, off);
            r1 += __shfl_down_sync(0xffffffffu, r1, off);
        }
        if (lane == 0) {
            out[ES_E(v0)] = 1.f / (1.f + expf(-(r0 + bias)));
            out[ES_E(v1)] = 1.f / (1.f + expf(-(r1 + bias)));
        }
    }
    if (k < end) {
        int v = g_es[k];
        float4 a = pt4[(size_t)ES_S(v) * 32 + lane];
        float r = fmaxf(a.x + pbv.x, 0.f) * wv.x + fmaxf(a.y + pbv.y, 0.f) * wv.y
                + fmaxf(a.z + pbv.z, 0.f) * wv.z + fmaxf(a.w + pbv.w, 0.f) * wv.w;
#pragma unroll
        for (int off = 16; off; off >>= 1) r += __shfl_down_sync(0xffffffffu, r, off);
        if (lane == 0) out[ES_E(v)] = 1.f / (1.f + expf(-(r + bias)));
    }
}

// ---------------- launch ----------------
extern "C" void kernel_launch(void* const* d_in, const int* in_sizes, int n_in,
                              void* d_out, int out_size) {
    int off, iE, iT;
    if (in_sizes[0] == 2 * EE) { off = 2; iE = 0; iT = 1; }
    else                       { off = 0; iE = 24; iT = 25; }
    const int* ei = (const int*)d_in[iE];
    const int* et = (const int*)d_in[iT];
    const int* src = ei;
    const int* dst = ei + EE;
    const float* basis0 = (const float*)d_in[off + 0];
    const float* comp0  = (const float*)d_in[off + 1];
    const float* root0  = (const float*)d_in[off + 2];
    const float* rbias0 = (const float*)d_in[off + 3];
    const float* basis1 = (const float*)d_in[off + 4];
    const float* comp1  = (const float*)d_in[off + 5];
    const float* root1  = (const float*)d_in[off + 6];
    const float* rbias1 = (const float*)d_in[off + 7];
    const float* basis2 = (const float*)d_in[off + 8];
    const float* comp2  = (const float*)d_in[off + 9];
    const float* root2  = (const float*)d_in[off + 10];
    const float* rbias2 = (const float*)d_in[off + 11];
    const float* basis3 = (const float*)d_in[off + 12];
    const float* comp3  = (const float*)d_in[off + 13];
    const float* root3  = (const float*)d_in[off + 14];
    const float* rbias3 = (const float*)d_in[off + 15];
    const float* gw  = (const float*)d_in[off + 16];
    const float* gas = (const float*)d_in[off + 17];
    const float* gad = (const float*)d_in[off + 18];
    const float* gb  = (const float*)d_in[off + 19];
    const float* w1  = (const float*)d_in[off + 20];
    const float* b1  = (const float*)d_in[off + 21];
    const float* w2  = (const float*)d_in[off + 22];
    const float* b2  = (const float*)d_in[off + 23];
    float* out = (float*)d_out;

    pre_count_kernel<<<PRE_BLOCKS + CNT_BLOCKS, 256>>>(basis0, comp0, basis1, comp1,
                                                       basis2, comp2, basis3, comp3, dst);
    scan_kernel<<<1, 1024>>>();
    scatter_kernel<<<CNT_BLOCKS, 256>>>(src, dst, et);

    l0d1_kernel<<<NN / 8, 256>>>(root0, rbias0, root1, rbias1);
    a1d2_kernel<<<NN / 4, 256>>>(root2, rbias2);
    a2d3_kernel<<<NN / 4, 256>>>(root3, rbias3);

    agg3_gath_kernel<<<NN / 16, 512>>>(gw, gas, gad);
    gatagg_ptpb_kernel<<<NN / 16, 256>>>(gb, w1, b1);
    edge_out_kernel<<<NN / 8, 256>>>(w2, b2, out);
}